// round 10
// baseline (speedup 1.0000x reference)
#include <cuda_runtime.h>
#include <math.h>

// Problem constants
#define E   4096
#define BB  8          // batch
#define TJ  512        // columns per block in K1 (256 threads * float2)
#define TK  32         // rows per split in K1 (R7 shape: best measured K1)
#define NSPLIT (E / TK)   // 128 row-splits
#define NCOLB  (E / TJ)   // 8 column blocks

// Deterministic split-K scratch: [NSPLIT][BB][E] fp32 = 16 MB (cached -> L2)
__device__ float g_scratch[(size_t)NSPLIT * BB * E];

// ---------------------------------------------------------------------------
// K1 (R7 shape, cached scratch): stream w/alpha/hebb once (192 MB).
// Block: 32 rows x 512 cols, float2/thread, 64 regs, 4 blocks/SM, grid=1024.
// w/alpha: __ldcs (evict-first) so hebb + scratch stay L2-resident.
// ---------------------------------------------------------------------------
__global__ __launch_bounds__(256, 4)
void k1_partial_gemm(const float* __restrict__ yin,
                     const float* __restrict__ hebb,
                     const float* __restrict__ w,
                     const float* __restrict__ alpha)
{
    const int cb  = blockIdx.x;            // 0..NCOLB-1
    const int rb  = blockIdx.y;            // 0..NSPLIT-1
    const int tid = threadIdx.x;           // 0..255
    const int j0  = cb * TJ + tid * 2;     // this thread's 2 columns
    const int k0  = rb * TK;

    // Stage yin[b, k0:k0+TK] in smem (8*32 = 256 floats, one per thread)
    __shared__ float yin_s[BB][TK];
    {
        int b = tid / TK, k = tid % TK;    // tid < 256 = BB*TK exactly
        yin_s[b][k] = yin[(size_t)b * E + k0 + k];
    }
    __syncthreads();

    float accx[BB], accy[BB];
#pragma unroll
    for (int b = 0; b < BB; b++) { accx[b] = 0.f; accy[b] = 0.f; }

    const size_t base0 = (size_t)k0 * E + j0;
    const float2* wp = (const float2*)(w     + base0);
    const float2* ap = (const float2*)(alpha + base0);
    const float2* hp = (const float2*)(hebb  + base0);
    const int strideV = E / 2;             // float2 row stride

    // Depth-2 pipeline: rows k and k+1 in flight
    float2 w0 = __ldcs(wp);
    float2 a0 = __ldcs(ap);
    float2 h0 = __ldg (hp);
    float2 w1 = __ldcs(wp + strideV);
    float2 a1 = __ldcs(ap + strideV);
    float2 h1 = __ldg (hp + strideV);

#pragma unroll 8
    for (int k = 0; k < TK; k++) {
        float2 wn, an, hn;
        if (k + 2 < TK) {
            const int off = (k + 2) * strideV;
            wn = __ldcs(wp + off);
            an = __ldcs(ap + off);
            hn = __ldg (hp + off);
        }

        const float mx = fmaf(a0.x, h0.x, w0.x);
        const float my = fmaf(a0.y, h0.y, w0.y);
#pragma unroll
        for (int b = 0; b < BB; b++) {
            const float yv = yin_s[b][k];
            accx[b] = fmaf(yv, mx, accx[b]);
            accy[b] = fmaf(yv, my, accy[b]);
        }

        w0 = w1; a0 = a1; h0 = h1;
        w1 = wn; a1 = an; h1 = hn;
    }

    // Normal cached stores: scratch targeted to stay L2-resident for K2
#pragma unroll
    for (int b = 0; b < BB; b++) {
        float2 v = make_float2(accx[b], accy[b]);
        *(float2*)(g_scratch + ((size_t)rb * BB + b) * E + j0) = v;
    }
}

// ---------------------------------------------------------------------------
// K2: reduce 128 splits + input, tanh -> yout (written to d_out[0 : BB*E])
// ---------------------------------------------------------------------------
__global__ __launch_bounds__(256)
void k2_yout(const float* __restrict__ input, float* __restrict__ yout)
{
    const int idx = blockIdx.x * 256 + threadIdx.x;  // 0 .. BB*E-1
    if (idx >= BB * E) return;
    float s = input[idx];
#pragma unroll 8
    for (int r = 0; r < NSPLIT; r++)
        s += g_scratch[(size_t)r * BB * E + idx];
    yout[idx] = tanhf(s);
}

// ---------------------------------------------------------------------------
// K3 (R9 winner): hebb_new = (1-eta)*hebb + eta * yin0 (outer) yout0.
// Reverse block order (MRU-first hebb reads -> L2 hits from K1) and __stcs
// output stores (don't evict not-yet-read hebb lines).
// ---------------------------------------------------------------------------
__global__ __launch_bounds__(256)
void k3_hebb(const float* __restrict__ hebb,
             const float* __restrict__ yin,    // row 0 used
             const float* __restrict__ eta,    // scalar
             const float* __restrict__ yout0,  // d_out row 0 (E floats)
             float* __restrict__ hebb_out)
{
    const float et    = eta[0];
    const float one_m = 1.0f - et;

    const int n4   = (E * E) / 4;
    const int rblk = gridDim.x - 1 - blockIdx.x;      // reverse block order
    const int t    = rblk * 256 + threadIdx.x;        // one float4 per thread
    if (t >= n4) return;

    const int row = t / (E / 4);
    const int c4  = t % (E / 4);
    const float s = et * yin[row];                    // eta * yin0[row]

    const float4 h = *(const float4*)(hebb + (size_t)t * 4);   // want L2 hits
    const float4 y = __ldg((const float4*)(yout0 + (size_t)c4 * 4));
    float4 o;
    o.x = fmaf(one_m, h.x, s * y.x);
    o.y = fmaf(one_m, h.y, s * y.y);
    o.z = fmaf(one_m, h.z, s * y.z);
    o.w = fmaf(one_m, h.w, s * y.w);
    __stcs((float4*)(hebb_out + (size_t)t * 4), o);
}

// ---------------------------------------------------------------------------
// Launch: inputs in metadata order: input, yin, hebb, w, alpha, eta
// Output: [yout (8*4096) | hebb_new (4096*4096)] fp32
// ---------------------------------------------------------------------------
extern "C" void kernel_launch(void* const* d_in, const int* in_sizes, int n_in,
                              void* d_out, int out_size)
{
    const float* input = (const float*)d_in[0];
    const float* yin   = (const float*)d_in[1];
    const float* hebb  = (const float*)d_in[2];
    const float* w     = (const float*)d_in[3];
    const float* alpha = (const float*)d_in[4];
    const float* eta   = (const float*)d_in[5];

    float* out      = (float*)d_out;
    float* yout     = out;            // BB*E
    float* hebb_out = out + BB * E;   // E*E

    // K1: 8 col-blocks x 128 row-splits = 1024 blocks x 256 threads
    dim3 g1(NCOLB, NSPLIT);
    k1_partial_gemm<<<g1, 256>>>(yin, hebb, w, alpha);

    // K2: 32768 elems
    k2_yout<<<(BB * E + 255) / 256, 256>>>(input, yout);

    // K3: E*E/4 float4 threads, reverse-ordered blocks
    const int n4 = (E * E) / 4;
    k3_hebb<<<(n4 + 255) / 256, 256>>>(hebb, yin, eta, yout, hebb_out);
}

// round 11
// speedup vs baseline: 1.0620x; 1.0620x over previous
#include <cuda_runtime.h>
#include <math.h>

// Problem constants
#define E   4096
#define BB  8          // batch
#define TJ  512        // columns per block in K1 (256 threads * float2)
#define TK  32         // rows per split in K1 (best measured K1 shape)
#define NSPLIT (E / TK)   // 128 row-splits
#define NCOLB  (E / TJ)   // 8 column blocks

// Deterministic split-K scratch: [NSPLIT][BB][E] fp32 = 16 MB
__device__ float g_scratch[(size_t)NSPLIT * BB * E];

// ---------------------------------------------------------------------------
// K1 (reproduced 38.8us): stream w/alpha/hebb once (192 MB).
// Block: 32 rows x 512 cols, float2/thread, 64 regs, 4 blocks/SM, grid=1024.
// w/alpha: __ldcs (evict-first) so hebb stays L2-resident for K3.
// ---------------------------------------------------------------------------
__global__ __launch_bounds__(256, 4)
void k1_partial_gemm(const float* __restrict__ yin,
                     const float* __restrict__ hebb,
                     const float* __restrict__ w,
                     const float* __restrict__ alpha)
{
    const int cb  = blockIdx.x;            // 0..NCOLB-1
    const int rb  = blockIdx.y;            // 0..NSPLIT-1
    const int tid = threadIdx.x;           // 0..255
    const int j0  = cb * TJ + tid * 2;     // this thread's 2 columns
    const int k0  = rb * TK;

    // Stage yin[b, k0:k0+TK] in smem (8*32 = 256 floats, one per thread)
    __shared__ float yin_s[BB][TK];
    {
        int b = tid / TK, k = tid % TK;    // tid < 256 = BB*TK exactly
        yin_s[b][k] = yin[(size_t)b * E + k0 + k];
    }
    __syncthreads();

    float accx[BB], accy[BB];
#pragma unroll
    for (int b = 0; b < BB; b++) { accx[b] = 0.f; accy[b] = 0.f; }

    const size_t base0 = (size_t)k0 * E + j0;
    const float2* wp = (const float2*)(w     + base0);
    const float2* ap = (const float2*)(alpha + base0);
    const float2* hp = (const float2*)(hebb  + base0);
    const int strideV = E / 2;             // float2 row stride

    // Depth-2 pipeline: rows k and k+1 in flight
    float2 w0 = __ldcs(wp);
    float2 a0 = __ldcs(ap);
    float2 h0 = __ldg (hp);
    float2 w1 = __ldcs(wp + strideV);
    float2 a1 = __ldcs(ap + strideV);
    float2 h1 = __ldg (hp + strideV);

#pragma unroll 8
    for (int k = 0; k < TK; k++) {
        float2 wn, an, hn;
        if (k + 2 < TK) {
            const int off = (k + 2) * strideV;
            wn = __ldcs(wp + off);
            an = __ldcs(ap + off);
            hn = __ldg (hp + off);
        }

        const float mx = fmaf(a0.x, h0.x, w0.x);
        const float my = fmaf(a0.y, h0.y, w0.y);
#pragma unroll
        for (int b = 0; b < BB; b++) {
            const float yv = yin_s[b][k];
            accx[b] = fmaf(yv, mx, accx[b]);
            accy[b] = fmaf(yv, my, accy[b]);
        }

        w0 = w1; a0 = a1; h0 = h1;
        w1 = wn; a1 = an; h1 = hn;
    }

#pragma unroll
    for (int b = 0; b < BB; b++) {
        float2 v = make_float2(accx[b], accy[b]);
        *(float2*)(g_scratch + ((size_t)rb * BB + b) * E + j0) = v;
    }
}

// ---------------------------------------------------------------------------
// K2 (parallel reduction): 1024 blocks x 256 threads.
// Block owns 32 consecutive outputs; warp w sums splits [w*16, w*16+16)
// with coalesced 128B loads; 8x32 smem reduce; warp 0 adds input + tanh.
// ---------------------------------------------------------------------------
#define K2_OUTS 32
#define K2_SPW  (NSPLIT / 8)   // 16 splits per warp

__global__ __launch_bounds__(256)
void k2_yout(const float* __restrict__ input, float* __restrict__ yout)
{
    const int wid  = threadIdx.x >> 5;         // 0..7
    const int lane = threadIdx.x & 31;         // 0..31
    const int base = blockIdx.x * K2_OUTS;     // first output of this block
    const int idx  = base + lane;              // this lane's output elem

    float s = 0.f;
    const int r0 = wid * K2_SPW;
#pragma unroll
    for (int r = 0; r < K2_SPW; r++)
        s += g_scratch[(size_t)(r0 + r) * BB * E + idx];

    __shared__ float red[8][K2_OUTS];
    red[wid][lane] = s;
    __syncthreads();

    if (wid == 0) {
        float t = input[idx];
#pragma unroll
        for (int ww = 0; ww < 8; ww++)
            t += red[ww][lane];
        yout[idx] = tanhf(t);
    }
}

// ---------------------------------------------------------------------------
// K3 (R9 winner): hebb_new = (1-eta)*hebb + eta * yin0 (outer) yout0.
// Reverse block order (MRU-first hebb reads -> L2 hits from K1) and __stcs
// output stores (don't evict not-yet-read hebb lines).
// ---------------------------------------------------------------------------
__global__ __launch_bounds__(256)
void k3_hebb(const float* __restrict__ hebb,
             const float* __restrict__ yin,    // row 0 used
             const float* __restrict__ eta,    // scalar
             const float* __restrict__ yout0,  // d_out row 0 (E floats)
             float* __restrict__ hebb_out)
{
    const float et    = eta[0];
    const float one_m = 1.0f - et;

    const int n4   = (E * E) / 4;
    const int rblk = gridDim.x - 1 - blockIdx.x;      // reverse block order
    const int t    = rblk * 256 + threadIdx.x;        // one float4 per thread
    if (t >= n4) return;

    const int row = t / (E / 4);
    const int c4  = t % (E / 4);
    const float s = et * yin[row];                    // eta * yin0[row]

    const float4 h = *(const float4*)(hebb + (size_t)t * 4);   // want L2 hits
    const float4 y = __ldg((const float4*)(yout0 + (size_t)c4 * 4));
    float4 o;
    o.x = fmaf(one_m, h.x, s * y.x);
    o.y = fmaf(one_m, h.y, s * y.y);
    o.z = fmaf(one_m, h.z, s * y.z);
    o.w = fmaf(one_m, h.w, s * y.w);
    __stcs((float4*)(hebb_out + (size_t)t * 4), o);
}

// ---------------------------------------------------------------------------
// Launch: inputs in metadata order: input, yin, hebb, w, alpha, eta
// Output: [yout (8*4096) | hebb_new (4096*4096)] fp32
// ---------------------------------------------------------------------------
extern "C" void kernel_launch(void* const* d_in, const int* in_sizes, int n_in,
                              void* d_out, int out_size)
{
    const float* input = (const float*)d_in[0];
    const float* yin   = (const float*)d_in[1];
    const float* hebb  = (const float*)d_in[2];
    const float* w     = (const float*)d_in[3];
    const float* alpha = (const float*)d_in[4];
    const float* eta   = (const float*)d_in[5];

    float* out      = (float*)d_out;
    float* yout     = out;            // BB*E
    float* hebb_out = out + BB * E;   // E*E

    // K1: 8 col-blocks x 128 row-splits = 1024 blocks x 256 threads
    dim3 g1(NCOLB, NSPLIT);
    k1_partial_gemm<<<g1, 256>>>(yin, hebb, w, alpha);

    // K2: 32768 outputs / 32 per block = 1024 blocks
    k2_yout<<<(BB * E) / K2_OUTS, 256>>>(input, yout);

    // K3: E*E/4 float4 threads, reverse-ordered blocks
    const int n4 = (E * E) / 4;
    k3_hebb<<<(n4 + 255) / 256, 256>>>(hebb, yin, eta, yout, hebb_out);
}